// round 17
// baseline (speedup 1.0000x reference)
#include <cuda_runtime.h>
#include <cstddef>

using ull = unsigned long long;

// Problem constants
constexpr int B_   = 64;
constexpr int T_   = 2048;
constexpr int H_   = 100;
constexpr int IN_  = 10;
constexpr int OUT_ = 10;
constexpr int L_   = 5;
constexpr int M_   = B_ * T_;          // 131072 rows

constexpr int TC_  = 32;               // timesteps per chunk
constexpr int NC_  = T_ / TC_;         // 64 chunks

// Scratch (device globals: no allocation anywhere)
__device__ float g_xpc[2 * L_ * B_ * TC_ * H_];      // xp chunks, parity by c&1
__device__ int   g_prodF[L_ * B_];                   // chunks produced for layer li
__device__ int   g_consF[L_ * B_];                   // chunks consumed by layer li

// ---------------------------------------------------------------------------
// Packed f32x2 helpers (sm_103a FFMA2/FADD2 via PTX)
// ---------------------------------------------------------------------------
__device__ __forceinline__ ull ffma2(ull a, ull b, ull c) {
    ull d;
    asm("fma.rn.f32x2 %0, %1, %2, %3;" : "=l"(d) : "l"(a), "l"(b), "l"(c));
    return d;
}
__device__ __forceinline__ ull addf2(ull a, ull b) {
    ull d;
    asm("add.rn.f32x2 %0, %1, %2;" : "=l"(d) : "l"(a), "l"(b));
    return d;
}
__device__ __forceinline__ ull pack2(float lo, float hi) {
    ull r;
    asm("mov.b64 %0, {%1, %2};" : "=l"(r) : "f"(lo), "f"(hi));
    return r;
}
__device__ __forceinline__ float lo2(ull v) {
    return __uint_as_float((unsigned)(v & 0xFFFFFFFFull));
}
__device__ __forceinline__ float hi2(ull v) {
    return __uint_as_float((unsigned)(v >> 32));
}

// ---------------------------------------------------------------------------
// Short-chain overflow-safe tanh (validated R14/R15): tanh(x)=1-2/(e^{2x}+1).
//   x->+inf: e=inf -> rcp=0 -> 1.  x->-inf: e=0 -> rcp=1 -> -1.  ~1e-6 acc.
// ---------------------------------------------------------------------------
__device__ __forceinline__ float fast_tanh(float x) {
    float t = x * 2.8853900817779268f;     // 2*log2(e)*x
    float e, r;
    asm("ex2.approx.f32 %0, %1;" : "=f"(e) : "f"(t));
    asm("rcp.approx.f32 %0, %1;" : "=f"(r) : "f"(e + 1.0f));
    return fmaf(-2.0f, r, 1.0f);
}

// Batched dot over 100 floats: operands smem (broadcast), weights in regs.
__device__ __forceinline__ float dot100(const ulonglong2* __restrict__ hp,
                                        const ulonglong2* __restrict__ w,
                                        ull a0) {
    ull a1 = 0ull, a2 = 0ull, a3 = 0ull;
    ulonglong2 hv[13];
    #pragma unroll
    for (int i = 0; i < 13; i++) hv[i] = hp[i];
    #pragma unroll
    for (int i = 0; i < 13; i++) {
        if (i & 1) { a2 = ffma2(w[i].x, hv[i].x, a2);
                     a3 = ffma2(w[i].y, hv[i].y, a3); }
        else       { a0 = ffma2(w[i].x, hv[i].x, a0);
                     a1 = ffma2(w[i].y, hv[i].y, a1); }
    }
    #pragma unroll
    for (int i = 0; i < 12; i++) hv[i] = hp[13 + i];
    #pragma unroll
    for (int i = 0; i < 12; i++) {
        if (i & 1) { a3 = ffma2(w[13 + i].x, hv[i].x, a3);
                     a2 = ffma2(w[13 + i].y, hv[i].y, a2); }
        else       { a1 = ffma2(w[13 + i].x, hv[i].x, a1);
                     a0 = ffma2(w[13 + i].y, hv[i].y, a0); }
    }
    const ull s = addf2(addf2(a0, a2), addf2(a1, a3));
    return lo2(s) + hi2(s);
}

// ---------------------------------------------------------------------------
// Init: zero the pipeline flags (runs at the head of every replay).
// ---------------------------------------------------------------------------
__global__ void init_k()
{
    const int i = threadIdx.x;
    if (i < L_ * B_) { g_prodF[i] = 0; g_consF[i] = 0; }
}

// ---------------------------------------------------------------------------
// Persistent pipeline kernel — R16 structure with layer-0 GEMM fused in.
// 320 CTAs (li = bid>>6, b = bid&63) x 128 threads; per chunk c:
//   acquire xp:
//     li==0: stage x chunk (TC x 10 floats) into smem, then each thread
//            computes xp_s[t][j] = dot10(W_ih0[j], x_t) + bias (W_ih0 row =
//            5 ull regs, reloaded per chunk -> live range disjoint from whh).
//     li>0 : wait prodF >= c+1, float4-copy xpc slot c&1 -> xp_s, release
//            consF (early: copy IS the consumption).
//   scan: reload whh per chunk (R13-proven reg discipline), TC recurrent
//     steps, h_s double-buffered, h_t stashed into xp_s rows.
//   phase B: li<4 -> producer dots into xpc (wih regs, per-chunk reload,
//            backpressure-wait consF[li+1] >= c-1 first);
//            li==4 -> fused projection to y from xp_s stash + wout_s (smem).
// Residency: 128 thr, ~155 regs (<=168 cap), ~18.5 KB smem -> 3 CTAs/SM =
// 444 slots >= 320 -> full wave-1 placement; dep indices strictly decrease.
// ---------------------------------------------------------------------------
__global__ void __launch_bounds__(128, 3)
persist_k(const float* __restrict__ x, float* __restrict__ xpc,
          const float* __restrict__ W_ih0,
          const float* __restrict__ W_ih, const float* __restrict__ W_hh,
          const float* __restrict__ b_ih, const float* __restrict__ b_hh,
          const float* __restrict__ W_out, const float* __restrict__ b_out,
          const float* __restrict__ h0all,
          float* __restrict__ y, float* __restrict__ hfin)
{
    const int li = blockIdx.x >> 6;          // 0..4
    const int b  = blockIdx.x & 63;

    __shared__ __align__(16) float xp_s[TC_ * H_];    // 12800 B
    __shared__ __align__(16) float x_s[TC_ * IN_];    //  1280 B (li==0)
    __shared__ __align__(16) float h_s[2][104];       //    832 B
    __shared__ __align__(16) float wout_s[OUT_ * H_]; //  4000 B (li==4)
    __shared__ float bout_s[OUT_];

    const int tid = threadIdx.x;
    const int j   = tid;
    const bool act = (j < H_);
    const int jr  = act ? j : 0;

    volatile int* prodF = (volatile int*)g_prodF;
    volatile int* consF = (volatile int*)g_consF;

    // stage projection weights into smem once (li==4 CTAs only; ordered
    // before first use by the syncthreads inside chunk 0)
    if (li == L_ - 1) {
        for (int i = tid; i < OUT_ * H_; i += 128) wout_s[i] = W_out[i];
        if (tid < OUT_) bout_s[tid] = b_out[tid];
    }

    // h init (once; h_s persists across chunks)
    if (act) h_s[0][j] = h0all[((size_t)li * B_ + b) * H_ + j];

    float bias0 = 0.0f;                      // layer-0 gemm bias
    if (li == 0 && act) bias0 = b_ih[j] + b_hh[j];

    float bias2 = 0.0f;                      // producer bias (li<4)
    if (li < L_ - 1 && act)
        bias2 = b_ih[(li + 1) * H_ + j] + b_hh[(li + 1) * H_ + j];

    for (int c = 0; c < NC_; c++) {
        const int t0  = c * TC_;
        const int par = c & 1;

        // ---- acquire xp chunk into smem ----
        if (li == 0) {
            // stage x chunk (TC x 10 floats = 80 float4, 16B-aligned)
            {
                const float4* s4 = reinterpret_cast<const float4*>(
                    x + ((size_t)b * T_ + t0) * IN_);
                float4* d4 = reinterpret_cast<float4*>(x_s);
                for (int i = tid; i < TC_ * IN_ / 4; i += 128) d4[i] = s4[i];
            }
            __syncthreads();
            // mini-GEMM: xp_s[t][j] = bias0 + dot10(W_ih0 row j, x_t)
            if (act) {
                ull w5[5];                   // reloaded per chunk (L2-hot)
                const ull* wp = reinterpret_cast<const ull*>(
                    W_ih0 + (size_t)j * IN_);
                #pragma unroll
                for (int i = 0; i < 5; i++) w5[i] = wp[i];

                for (int t = 0; t < TC_; t++) {
                    const ull* xv = reinterpret_cast<const ull*>(x_s + t * IN_);
                    ull a0 = 0ull, a1 = 0ull;
                    a0 = ffma2(w5[0], xv[0], a0);
                    a1 = ffma2(w5[1], xv[1], a1);
                    a0 = ffma2(w5[2], xv[2], a0);
                    a1 = ffma2(w5[3], xv[3], a1);
                    a0 = ffma2(w5[4], xv[4], a0);
                    const ull s = addf2(a0, a1);
                    xp_s[t * H_ + j] = bias0 + lo2(s) + hi2(s);
                }
            }
        } else {
            if (tid == 0) {
                while (prodF[li * B_ + b] < c + 1) __nanosleep(32);
            }
            __syncthreads();
            __threadfence();
            {
                const float* src =
                    xpc + (((size_t)par * L_ + li) * B_ + b) * (TC_ * H_);
                const float4* s4 = reinterpret_cast<const float4*>(src);
                float4* d4 = reinterpret_cast<float4*>(xp_s);
                for (int i = tid; i < TC_ * H_ / 4; i += 128) d4[i] = s4[i];
            }
        }
        __syncthreads();
        if (li > 0 && tid == 0) {
            __threadfence();
            atomicExch(&g_consF[li * B_ + b], c + 1);
        }

        // ---- W_hh row (reloaded per chunk: keeps live ranges disjoint
        //      from wih/w5 so regs stay under the 168 cap) ----
        ulonglong2 whh[25];
        #pragma unroll
        for (int i = 0; i < 25; i++) { whh[i].x = 0ull; whh[i].y = 0ull; }
        if (act) {
            const ulonglong2* wp = reinterpret_cast<const ulonglong2*>(
                W_hh + ((size_t)li * H_ + j) * H_);
            #pragma unroll
            for (int i = 0; i < 25; i++) whh[i] = wp[i];
        }
        __syncthreads();   // xp_s ready for all; h_s ready

        // ---- TC recurrent steps ----
        int cur = 0;
        float th = 0.0f;

        for (int t = 0; t < TC_; t++) {
            const ull a0 = pack2(xp_s[t * H_ + jr], 0.0f);
            const float sum = dot100(
                reinterpret_cast<const ulonglong2*>(h_s[cur]), whh, a0);
            th = fast_tanh(sum);

            if (act) {
                h_s[cur ^ 1][j] = th;
                xp_s[t * H_ + j] = th;                // stash h_t for phase B
            }
            __syncthreads();
            cur ^= 1;
        }

        if (act && c == NC_ - 1)
            hfin[((size_t)li * B_ + b) * H_ + j] = th;

        // ---- phase B ----
        if (li < L_ - 1) {
            // backpressure: slot par was last read by consumer chunk c-2
            if (c >= 2) {
                if (tid == 0) {
                    while (consF[(li + 1) * B_ + b] < c - 1) __nanosleep(32);
                }
                __syncthreads();
                __threadfence();
            }

            ulonglong2 wih[25];
            #pragma unroll
            for (int i = 0; i < 25; i++) { wih[i].x = 0ull; wih[i].y = 0ull; }
            if (act) {
                const ulonglong2* wp = reinterpret_cast<const ulonglong2*>(
                    W_ih + ((size_t)li * H_ + j) * H_);   // W_ih[(li+1)-1]
                #pragma unroll
                for (int i = 0; i < 25; i++) wih[i] = wp[i];
            }

            float* dst = xpc +
                (((size_t)par * L_ + (li + 1)) * B_ + b) * (TC_ * H_);

            #pragma unroll 2
            for (int t = 0; t < TC_; t++) {
                const float sum = dot100(
                    reinterpret_cast<const ulonglong2*>(xp_s + t * H_),
                    wih, 0ull);
                if (act) dst[t * H_ + j] = bias2 + sum;
            }

            __syncthreads();
            if (tid == 0) {
                __threadfence();
                atomicExch(&g_prodF[(li + 1) * B_ + b], c + 1);
            }
        } else {
            // FUSED PROJECTION (smem weights -> no new register arrays):
            // y[b][t0+t][o] = bout[o] + dot(W_out[o,:], h_t)
            if (tid < 120) {
                const int o  = tid % OUT_;        // output column
                const int pt = tid / OUT_;        // row group 0..11
                float* yrow = y + ((size_t)b * T_ + t0) * OUT_;
                const float4* wo4 =
                    reinterpret_cast<const float4*>(wout_s + o * H_);
                const float biasO = bout_s[o];

                for (int t = pt; t < TC_; t += 12) {
                    const float4* hr4 =
                        reinterpret_cast<const float4*>(xp_s + t * H_);
                    float acc = biasO;
                    #pragma unroll
                    for (int k = 0; k < H_ / 4; k++) {
                        const float4 wv = wo4[k];
                        const float4 hv = hr4[k];
                        acc += wv.x * hv.x;
                        acc += wv.y * hv.y;
                        acc += wv.z * hv.z;
                        acc += wv.w * hv.w;
                    }
                    yrow[t * OUT_ + o] = acc;
                }
            }
            __syncthreads();   // xp_s reusable next chunk
        }
    }
}

// ---------------------------------------------------------------------------
// kernel_launch: 2 plain default-stream launches (init flags, persistent
// pipeline with fused layer-0 gemm + fused projection). Capture-safe APIs
// only. Output: concat( y [B,T,OUT] , h_finals [L,B,H] )
// ---------------------------------------------------------------------------
extern "C" void kernel_launch(void* const* d_in, const int* in_sizes, int n_in,
                              void* d_out, int out_size)
{
    const float* x           = (const float*)d_in[0];
    const float* hidden_prev = (const float*)d_in[1];
    const float* W_ih0       = (const float*)d_in[2];
    const float* W_ih        = (const float*)d_in[3];
    const float* W_hh        = (const float*)d_in[4];
    const float* b_ih        = (const float*)d_in[5];
    const float* b_hh        = (const float*)d_in[6];
    const float* W_out       = (const float*)d_in[7];
    const float* b_out       = (const float*)d_in[8];

    float* out  = (float*)d_out;
    float* y    = out;
    float* hfin = out + (size_t)M_ * OUT_;

    float* xpc;
    cudaGetSymbolAddress((void**)&xpc, g_xpc);

    // Zero pipeline flags (fresh for every replay).
    init_k<<<1, 512>>>();

    // Persistent wavefront pipeline: all layers, all chunks, everything fused.
    persist_k<<<L_ * B_, 128>>>(x, xpc, W_ih0,
                                W_ih, W_hh, b_ih, b_hh,
                                W_out, b_out,
                                hidden_prev, y, hfin);
}